// round 14
// baseline (speedup 1.0000x reference)
#include <cuda_runtime.h>
#include <cuda_fp16.h>
#include <cstdint>
#include <math.h>

// Problem constants
#define B_    2
#define N_    8192
#define C_    256
#define HEADS_ 8
#define DH_   32
#define HM_   128
#define HW_   (HM_*HM_)
#define NS_   1024
#define KCOL_ 4096
#define KSPL_ 8
#define KCH_  (KCOL_/KSPL_)   // 512

// ---------------- scratch (device globals) ------------------------------------
__device__ float g_Fmap[B_ * HW_ * C_];
__device__ float g_Cnt [B_ * HW_];
__device__ float g_Xm  [B_ * HW_ * C_];
__device__ float g_Wc  [C_ * KCOL_];
__device__ float g_Wkv [2 * C_ * C_];
__device__ float g_CPart[KSPL_ * B_ * NS_ * C_];
__device__ float g_Xs  [B_ * NS_ * C_];
__device__ float g_Q   [B_ * N_ * C_];
__device__ uint32_t g_KhW[16 * NS_ * 16];
__device__ uint32_t g_VtW[16 * 32 * 512];
__device__ float g_AO  [B_ * N_ * C_];

// ================= fp16 mma helpers ===========================================
__device__ __forceinline__ uint32_t pkh2(float a, float b) {
    __half2 h = __floats2half2_rn(a, b);
    return *(uint32_t*)&h;
}
__device__ __forceinline__ void f16split(float x, float& hi, float& lo) {
    float h = __half2float(__float2half_rn(x));
    hi = h; lo = x - h;
}
__device__ __forceinline__ void mma16(float* c, const uint32_t* a, const uint32_t* b) {
    asm volatile(
        "mma.sync.aligned.m16n8k16.row.col.f32.f16.f16.f32 "
        "{%0,%1,%2,%3}, {%4,%5,%6,%7}, {%8,%9}, {%0,%1,%2,%3};"
        : "+f"(c[0]), "+f"(c[1]), "+f"(c[2]), "+f"(c[3])
        : "r"(a[0]), "r"(a[1]), "r"(a[2]), "r"(a[3]), "r"(b[0]), "r"(b[1]));
}

// implicit-im2col address for conv A
__device__ __forceinline__ const float* convA_addr(int m, int k) {
    int b = m >> 10, rr = m & 1023;
    int oy = rr >> 5, ox = rr & 31;
    int kk = k >> 8, ci = k & 255;
    int ky = kk >> 2, kx = kk & 3;
    int pix = (b << 14) + (oy * 4 + ky) * HM_ + ox * 4 + kx;
    return g_Xm + (size_t)pix * 256 + ci;
}

// ================= asymmetric fp16 GEMM body (128x128, 512 threads) ===========
// 16 warps, warp tile 32x32 (WM_T=2, WN_T=4). Double-buffered.
// EPI 0: C = A@B^T (+bias).  EPI 2: kv-pack epilogue.
template<bool CONVA, int EPI>
__device__ __forceinline__ void gemm_body(
        const float* __restrict__ A, int lda, int kbase,
        const float* __restrict__ Bw, int ldb,
        float* __restrict__ Cb, int ldc,
        int K, const float* __restrict__ bias, int n0, int m0) {
    constexpr int BN = 128;
    constexpr int WM_T = 2, WN_T = 4;
    constexpr int ES = BN + 4;
    constexpr int STW = 128 * 20 * 2 + BN * 20;

    extern __shared__ float smem[];
    uint32_t* stage0 = (uint32_t*)smem;
    float* epi = smem;

    const int t = threadIdx.x, lane = t & 31, warp = t >> 5;
    const int g = lane >> 2, tig = lane & 3;
    const int warpM = warp >> 2, warpN = warp & 3;      // 4x4 warps
    const int wrb = warpM * 32, wcb = warpN * 32;

    const int lr = t >> 2;              // 0..127
    const int lc = (t & 3) * 8;         // 0,8,16,24

    float acc[WM_T][WN_T][4];
#pragma unroll
    for (int i = 0; i < WM_T; i++)
#pragma unroll
        for (int j = 0; j < WN_T; j++)
#pragma unroll
            for (int q = 0; q < 4; q++) acc[i][j][q] = 0.f;

    const int nc = K >> 5;
    float4 pa[2], pb[2];

#define GB_LOAD(cc_)                                                              \
    {                                                                             \
        int k0_ = (cc_) << 5;                                                     \
        if (CONVA) {                                                              \
            pa[0] = *(const float4*)convA_addr(m0 + lr, kbase + k0_ + lc);        \
            pa[1] = *(const float4*)convA_addr(m0 + lr, kbase + k0_ + lc + 4);    \
        } else {                                                                  \
            pa[0] = *(const float4*)(A + (size_t)(m0 + lr) * lda + k0_ + lc);     \
            pa[1] = *(const float4*)(A + (size_t)(m0 + lr) * lda + k0_ + lc + 4); \
        }                                                                         \
        pb[0] = *(const float4*)(Bw + (size_t)(n0 + lr) * ldb + kbase + k0_ + lc);     \
        pb[1] = *(const float4*)(Bw + (size_t)(n0 + lr) * ldb + kbase + k0_ + lc + 4); \
    }

#define GB_STORE(st_)                                                             \
    {                                                                             \
        uint32_t* AshW_ = stage0 + (st_) * STW;                                   \
        uint32_t* AslW_ = AshW_ + 128 * 20;                                       \
        uint32_t* BshW_ = AslW_ + 128 * 20;                                       \
        _Pragma("unroll")                                                         \
        for (int i = 0; i < 2; i++) {                                             \
            float h0, l0, h1, l1, h2, l2, h3, l3;                                 \
            f16split(pa[i].x, h0, l0); f16split(pa[i].y, h1, l1);                 \
            f16split(pa[i].z, h2, l2); f16split(pa[i].w, h3, l3);                 \
            *(uint2*)&AshW_[lr * 20 + ((lc + i * 4) >> 1)] = make_uint2(pkh2(h0, h1), pkh2(h2, h3)); \
            *(uint2*)&AslW_[lr * 20 + ((lc + i * 4) >> 1)] = make_uint2(pkh2(l0, l1), pkh2(l2, l3)); \
        }                                                                         \
        _Pragma("unroll")                                                         \
        for (int i = 0; i < 2; i++)                                               \
            *(uint2*)&BshW_[lr * 20 + ((lc + i * 4) >> 1)] =                      \
                make_uint2(pkh2(pb[i].x, pb[i].y), pkh2(pb[i].z, pb[i].w));       \
    }

    GB_LOAD(0);
    GB_STORE(0);
    __syncthreads();
    if (nc > 1) GB_LOAD(1);

    for (int c = 0; c < nc; c++) {
        const int st = c & 1;
        const uint32_t* AshW = stage0 + st * STW;
        const uint32_t* AslW = AshW + 128 * 20;
        const uint32_t* BshW = AslW + 128 * 20;
#pragma unroll
        for (int ks = 0; ks < 2; ks++) {
            const int w0 = ks * 8;
            uint32_t ah[WM_T][4], al[WM_T][4];
#pragma unroll
            for (int mt = 0; mt < WM_T; mt++) {
                int r0 = wrb + mt * 16;
                ah[mt][0] = AshW[(r0 + g) * 20 + w0 + tig];
                ah[mt][1] = AshW[(r0 + 8 + g) * 20 + w0 + tig];
                ah[mt][2] = AshW[(r0 + g) * 20 + w0 + 4 + tig];
                ah[mt][3] = AshW[(r0 + 8 + g) * 20 + w0 + 4 + tig];
                al[mt][0] = AslW[(r0 + g) * 20 + w0 + tig];
                al[mt][1] = AslW[(r0 + 8 + g) * 20 + w0 + tig];
                al[mt][2] = AslW[(r0 + g) * 20 + w0 + 4 + tig];
                al[mt][3] = AslW[(r0 + 8 + g) * 20 + w0 + 4 + tig];
            }
            uint32_t bh[WN_T][2];
#pragma unroll
            for (int nt = 0; nt < WN_T; nt++) {
                int nr = wcb + nt * 8 + g;
                bh[nt][0] = BshW[nr * 20 + w0 + tig];
                bh[nt][1] = BshW[nr * 20 + w0 + 4 + tig];
            }
#pragma unroll
            for (int mt = 0; mt < WM_T; mt++)
#pragma unroll
                for (int nt = 0; nt < WN_T; nt++) {
                    mma16(acc[mt][nt], ah[mt], bh[nt]);
                    mma16(acc[mt][nt], al[mt], bh[nt]);
                }
        }
        if (c + 1 < nc) {
            GB_STORE(st ^ 1);
            __syncthreads();
            if (c + 2 < nc) GB_LOAD(c + 2);
        }
    }
    __syncthreads();
#pragma unroll
    for (int mt = 0; mt < WM_T; mt++)
#pragma unroll
        for (int nt = 0; nt < WN_T; nt++) {
            int r = wrb + mt * 16 + g;
            int cc = wcb + nt * 8 + 2 * tig;
            epi[r * ES + cc] = acc[mt][nt][0];
            epi[r * ES + cc + 1] = acc[mt][nt][1];
            epi[(r + 8) * ES + cc] = acc[mt][nt][2];
            epi[(r + 8) * ES + cc + 1] = acc[mt][nt][3];
        }
    __syncthreads();

    if (EPI == 0) {
        for (int idx = t; idx < 128 * BN; idx += 512) {
            int r = idx / BN, cc = idx % BN;
            float v = epi[r * ES + cc];
            if (bias) v += bias[n0 + cc];
            Cb[(size_t)(m0 + r) * ldc + n0 + cc] = v;
        }
    } else {
        if (n0 < 256) {
            for (int u = t; u < 128 * 64; u += 512) {
                int r = u >> 6, wp = u & 63;
                int cc = 2 * wp;
                int dim = n0 + cc;
                int h = dim >> 5, w2 = (dim & 31) >> 1;
                int m = m0 + r;
                int b = m >> 10, key = m & 1023;
                g_KhW[((size_t)((b * 8 + h) * NS_ + key)) * 16 + w2] =
                    pkh2(epi[r * ES + cc], epi[r * ES + cc + 1]);
            }
        } else {
            for (int u = t; u < 64 * 128; u += 512) {
                int wl = u >> 7, cc = u & 127;
                int dim = n0 - 256 + cc;
                int h = dim >> 5, d = dim & 31;
                int m = m0 + 2 * wl;
                int b = m >> 10, keyloc = m & 1023;
                g_VtW[((size_t)((b * 8 + h) * 32 + d)) * 512 + (keyloc >> 1)] =
                    pkh2(epi[(2 * wl) * ES + cc], epi[(2 * wl + 1) * ES + cc]);
            }
        }
    }
#undef GB_LOAD
#undef GB_STORE
}

// ---- merged conv(split-K x8) + q-projection launch ----------------------------
__global__ void __launch_bounds__(512, 1)
conv_q_kernel(const float* __restrict__ x, const float* __restrict__ Wq) {
    if (blockIdx.y < 16) {
        int zh = blockIdx.z;
        gemm_body<true, 0>(
            nullptr, 0, zh * KCH_, g_Wc, KCOL_,
            g_CPart + (size_t)zh * (B_ * NS_ * C_), C_,
            KCH_, nullptr, blockIdx.x * 128, blockIdx.y * 128);
    } else {
        if (blockIdx.z) return;
        gemm_body<false, 0>(
            x, C_, 0, Wq, C_, g_Q, C_,
            C_, nullptr, blockIdx.x * 128, (blockIdx.y - 16) * 128);
    }
}

__global__ void __launch_bounds__(512, 1)
gemm_kernel(const float* __restrict__ A, int lda,
            const float* __restrict__ Bw, int ldb,
            float* __restrict__ Cm, int ldc,
            int K, const float* __restrict__ bias) {
    gemm_body<false, 0>(A, lda, 0, Bw, ldb, Cm, ldc, K, bias,
                        blockIdx.x * 128, blockIdx.y * 128);
}

__global__ void __launch_bounds__(512, 1)
kv_gemm_kernel(const float* __restrict__ A, const float* __restrict__ Bw) {
    gemm_body<false, 2>(A, C_, 0, Bw, C_, nullptr, 0, C_, nullptr,
                        blockIdx.x * 128, blockIdx.y * 128);
}

// ================= fused flash attention (R13: halved S tile, 2 CTAs/SM) ======
__global__ void __launch_bounds__(256, 2)
attn_fused(const float* __restrict__ conf) {
    extern __shared__ float smem[];
    uint32_t* QhW = (uint32_t*)smem;            // [128][20]
    uint32_t* QlW = QhW + 128 * 20;
    uint32_t* stg = QlW + 128 * 20;             // 2 stages: [128*20 K][32*68 V][128 conf]
    const int STW = 128 * 20 + 32 * 68 + 128;

    const int t = threadIdx.x, lane = t & 31, warp = t >> 5;
    const int g = lane >> 2, tig = lane & 3;
    const int bh = blockIdx.y, b = bh >> 3, h = bh & 7;
    const int m0 = blockIdx.x << 7;
    const int wrb = warp << 4;
    const float scale = 0.17677669529663687f;

    {
        const int lr = t >> 3, lc = (t & 7) * 4;
#pragma unroll
        for (int i = 0; i < 4; i++) {
            int r = lr + i * 32;
            float4 v = *(const float4*)(g_Q + (size_t)(b * N_ + m0 + r) * C_ + h * DH_ + lc);
            float h0, l0, h1, l1, h2, l2, h3, l3;
            f16split(v.x * scale, h0, l0); f16split(v.y * scale, h1, l1);
            f16split(v.z * scale, h2, l2); f16split(v.w * scale, h3, l3);
            *(uint2*)&QhW[r * 20 + (lc >> 1)] = make_uint2(pkh2(h0, h1), pkh2(h2, h3));
            *(uint2*)&QlW[r * 20 + (lc >> 1)] = make_uint2(pkh2(l0, l1), pkh2(l2, l3));
        }
    }

    float Oacc[4][4];
#pragma unroll
    for (int i = 0; i < 4; i++)
#pragma unroll
        for (int j = 0; j < 4; j++) Oacc[i][j] = 0.f;
    float l0s = 0.f, l1s = 0.f;

    const uint4* KhG = (const uint4*)g_KhW;
    const uint4* VtG = (const uint4*)g_VtW;
    uint4 kr[2], vr[2];
    float cf;

#define AT_LOAD(kc_)                                                              \
    {                                                                             \
        int kb_ = (kc_) << 7;                                                     \
        _Pragma("unroll")                                                         \
        for (int i = 0; i < 2; i++) {                                             \
            int u = t + i * 256;                                                  \
            kr[i] = KhG[(size_t)(bh * NS_ + kb_ + (u >> 2)) * 4 + (u & 3)];       \
            vr[i] = VtG[(size_t)(bh * 32 + (u >> 4)) * 128 + (kc_) * 16 + (u & 15)]; \
        }                                                                         \
        if (t < 128) cf = conf[b * NS_ + kb_ + t];                                \
    }

#define AT_STORE(st_)                                                             \
    {                                                                             \
        uint32_t* KsW_ = stg + (st_) * STW;                                       \
        uint32_t* VsW_ = KsW_ + 128 * 20;                                         \
        float* cf_ = (float*)(VsW_ + 32 * 68);                                    \
        _Pragma("unroll")                                                         \
        for (int i = 0; i < 2; i++) {                                             \
            int u = t + i * 256;                                                  \
            *(uint4*)&KsW_[(u >> 2) * 20 + 4 * (u & 3)] = kr[i];                  \
            *(uint4*)&VsW_[(u >> 4) * 68 + 4 * (u & 15)] = vr[i];                 \
        }                                                                         \
        if (t < 128) cf_[t] = cf;                                                 \
    }

    AT_LOAD(0);
    AT_STORE(0);
    __syncthreads();
    AT_LOAD(1);

    for (int kc = 0; kc < 8; kc++) {
        const int st = kc & 1;
        const uint32_t* KsW = stg + st * STW;
        const uint32_t* VsW = KsW + 128 * 20;
        const float* confs = (const float*)(VsW + 32 * 68);

#pragma unroll
        for (int h2 = 0; h2 < 2; h2++) {
            float Sacc[8][4];
#pragma unroll
            for (int nt = 0; nt < 8; nt++)
#pragma unroll
                for (int q = 0; q < 4; q++) Sacc[nt][q] = 0.f;

#pragma unroll
            for (int ks = 0; ks < 2; ks++) {
                const int w0 = ks * 8;
                uint32_t ah[4], al[4];
                ah[0] = QhW[(wrb + g) * 20 + w0 + tig];
                ah[1] = QhW[(wrb + 8 + g) * 20 + w0 + tig];
                ah[2] = QhW[(wrb + g) * 20 + w0 + 4 + tig];
                ah[3] = QhW[(wrb + 8 + g) * 20 + w0 + 4 + tig];
                al[0] = QlW[(wrb + g) * 20 + w0 + tig];
                al[1] = QlW[(wrb + 8 + g) * 20 + w0 + tig];
                al[2] = QlW[(wrb + g) * 20 + w0 + 4 + tig];
                al[3] = QlW[(wrb + 8 + g) * 20 + w0 + 4 + tig];
#pragma unroll
                for (int nt = 0; nt < 8; nt++) {
                    int nr = (h2 * 8 + nt) * 8 + g;
                    uint32_t bv[2];
                    bv[0] = KsW[nr * 20 + w0 + tig];
                    bv[1] = KsW[nr * 20 + w0 + 4 + tig];
                    mma16(Sacc[nt], ah, bv);
                    mma16(Sacc[nt], al, bv);
                }
            }

#pragma unroll
            for (int jj = 0; jj < 4; jj++) {
                const int j = h2 * 4 + jj;
                const int nt0 = 2 * jj, nt1 = 2 * jj + 1;
                const int ng0 = h2 * 8 + nt0, ng1 = h2 * 8 + nt1;
                float ca0 = confs[ng0 * 8 + 2 * tig], cb0 = confs[ng0 * 8 + 2 * tig + 1];
                float ca1 = confs[ng1 * 8 + 2 * tig], cb1 = confs[ng1 * 8 + 2 * tig + 1];
                float p00 = __expf(Sacc[nt0][0] + ca0);
                float p01 = __expf(Sacc[nt0][1] + cb0);
                float p02 = __expf(Sacc[nt0][2] + ca0);
                float p03 = __expf(Sacc[nt0][3] + cb0);
                float p10 = __expf(Sacc[nt1][0] + ca1);
                float p11 = __expf(Sacc[nt1][1] + cb1);
                float p12 = __expf(Sacc[nt1][2] + ca1);
                float p13 = __expf(Sacc[nt1][3] + cb1);
                l0s += p00 + p01 + p10 + p11;
                l1s += p02 + p03 + p12 + p13;

                uint32_t a[4];
                a[0] = pkh2(p00, p01);
                a[1] = pkh2(p02, p03);
                a[2] = pkh2(p10, p11);
                a[3] = pkh2(p12, p13);
#pragma unroll
                for (int dt = 0; dt < 4; dt++) {
                    uint32_t bv[2];
                    bv[0] = VsW[(dt * 8 + g) * 68 + 8 * j + tig];
                    bv[1] = VsW[(dt * 8 + g) * 68 + 8 * j + 4 + tig];
                    mma16(Oacc[dt], a, bv);
                }
            }
        }

        if (kc + 1 < 8) {
            AT_STORE(st ^ 1);
            __syncthreads();
            if (kc + 2 < 8) AT_LOAD(kc + 2);
        }
    }
#undef AT_LOAD
#undef AT_STORE

    l0s += __shfl_xor_sync(~0u, l0s, 1); l0s += __shfl_xor_sync(~0u, l0s, 2);
    l1s += __shfl_xor_sync(~0u, l1s, 1); l1s += __shfl_xor_sync(~0u, l1s, 2);
    float r0inv = 1.f / l0s, r1inv = 1.f / l1s;

#pragma unroll
    for (int dt = 0; dt < 4; dt++) {
        int cc = h * DH_ + dt * 8 + 2 * tig;
        size_t rowa = (size_t)(b * N_ + m0 + wrb + g) * C_;
        size_t rowb = (size_t)(b * N_ + m0 + wrb + 8 + g) * C_;
        g_AO[rowa + cc]     = Oacc[dt][0] * r0inv;
        g_AO[rowa + cc + 1] = Oacc[dt][1] * r0inv;
        g_AO[rowb + cc]     = Oacc[dt][2] * r1inv;
        g_AO[rowb + cc + 1] = Oacc[dt][3] * r1inv;
    }
}

// ================= preprocessing ==============================================
__global__ void __launch_bounds__(256) scatter_kernel(const float* __restrict__ xs,
                                                      const float* __restrict__ loc) {
    const int tok0 = blockIdx.x << 3;
    const int c = threadIdx.x;
    int p[8];
#pragma unroll
    for (int i = 0; i < 8; i++) {
        int token = tok0 + i;
        int b = token >> 13;
        float lx = loc[(size_t)token * 2 + 0];
        float ly = loc[(size_t)token * 2 + 1];
        lx = fminf(fmaxf(lx, 0.f), 1.f) * 127.f;
        ly = fminf(fmaxf(ly, 0.f), 1.f) * 127.f;
        p[i] = (b << 14) + (int)rintf(ly) * HM_ + (int)rintf(lx);
    }
#pragma unroll
    for (int i = 0; i < 8; i++) {
        atomicAdd(&g_Fmap[(size_t)p[i] * C_ + c], xs[(size_t)(tok0 + i) * C_ + c]);
        if (c == 0) atomicAdd(&g_Cnt[p[i]], 1.0f);
    }
}

__global__ void __launch_bounds__(256) blur_fused_kernel() {
    __shared__ float sf[3][34][64];
    __shared__ float minv[3][34];
    __shared__ float msk[3][34];

    const int t = threadIdx.x;
    const int x0 = blockIdx.x << 5;
    const int y = blockIdx.y;
    const int b = blockIdx.z >> 2, cg = blockIdx.z & 3;
    const int cbase = cg << 6;

    if (t < 102) {
        int r = t / 34, px = t % 34;
        int gy = y + r - 1, gx = x0 + px - 1;
        float inv = 0.f, mk = 0.f;
        if (gy >= 0 && gy < HM_ && gx >= 0 && gx < HM_) {
            float cnt = g_Cnt[(b << 14) + gy * HM_ + gx];
            if (cnt > 0.f) { inv = 1.f / (cnt + 1e-6f); mk = 1.f; }
        }
        minv[r][px] = inv;
        msk[r][px] = mk;
    }
    __syncthreads();

    for (int idx = t; idx < 3 * 34 * 64; idx += 256) {
        int r = idx / (34 * 64);
        int rem = idx - r * (34 * 64);
        int px = rem >> 6, c = rem & 63;
        int gy = y + r - 1, gx = x0 + px - 1;
        float val = 0.f;
        if (gy >= 0 && gy < HM_ && gx >= 0 && gx < HM_) {
            int pix = (b << 14) + gy * HM_ + gx;
            val = g_Fmap[(size_t)pix * 256 + cbase + c] * minv[r][px];
        }
        sf[r][px][c] = val;
    }
    __syncthreads();

    const float e1 = 0.88249690258459546f;
    const float e2 = 0.77880078307140487f;
    const float nrm = 1.0f / (1.0f + 4.0f * e1 + 4.0f * e2);
    const float wc = nrm, we = e1 * nrm, wo = e2 * nrm;

    const int c = t & 63;
    const int pg = t >> 6;
#pragma unroll
    for (int i = 0; i < 8; i++) {
        int px = pg * 8 + i;
        int ps = px + 1;
        float msum =
            wo * (msk[0][ps - 1] + msk[0][ps + 1] + msk[2][ps - 1] + msk[2][ps + 1]) +
            we * (msk[0][ps] + msk[1][ps - 1] + msk[1][ps + 1] + msk[2][ps]) +
            wc * msk[1][ps];
        float fsum =
            wo * (sf[0][ps - 1][c] + sf[0][ps + 1][c] + sf[2][ps - 1][c] + sf[2][ps + 1][c]) +
            we * (sf[0][ps][c] + sf[1][ps - 1][c] + sf[1][ps + 1][c] + sf[2][ps][c]) +
            wc * sf[1][ps][c];
        float fint = (msum > 0.f) ? fsum / (msum + 1e-6f) : 0.f;
        float fc = sf[1][ps][c];
        float mc = msk[1][ps];
        int cp = (b << 14) + y * HM_ + x0 + px;
        g_Xm[(size_t)cp * 256 + cbase + c] = fc + (1.f - mc) * fint;
    }
}

__global__ void __launch_bounds__(256) wprep_kernel(const float* __restrict__ srw,
                                                    const float* __restrict__ Wk,
                                                    const float* __restrict__ Wv) {
    int blk = blockIdx.x;
    if (blk < 4096) {
        int idx = blk * 256 + threadIdx.x;
        int co = idx >> 12;
        int r = idx & 4095;
        int kk = r >> 8;
        int ci = r & 255;
        g_Wc[idx] = srw[(size_t)co * 4096 + ci * 16 + kk];
    } else {
        int idx = (blk - 4096) * 256 + threadIdx.x;
        int row = idx >> 8, c = idx & 255;
        g_Wkv[idx] = (row < 256) ? Wk[row * 256 + c] : Wv[(row - 256) * 256 + c];
    }
}

__global__ void __launch_bounds__(256) ln_kernel(const float* __restrict__ srb,
                                                 const float* __restrict__ lnw,
                                                 const float* __restrict__ lnb) {
    __shared__ float red[8];
    int row = blockIdx.x, c = threadIdx.x;
    int lane = c & 31, wrp = c >> 5;
    float v = srb[c];
#pragma unroll
    for (int s = 0; s < KSPL_; s++)
        v += g_CPart[(size_t)s * (B_ * NS_ * C_) + (size_t)row * C_ + c];
    float s = v;
#pragma unroll
    for (int o = 16; o; o >>= 1) s += __shfl_xor_sync(~0u, s, o);
    if (lane == 0) red[wrp] = s;
    __syncthreads();
    float mu = (red[0] + red[1] + red[2] + red[3] + red[4] + red[5] + red[6] + red[7]) * (1.f / 256.f);
    float d = v - mu;
    float s2 = d * d;
#pragma unroll
    for (int o = 16; o; o >>= 1) s2 += __shfl_xor_sync(~0u, s2, o);
    __syncthreads();
    if (lane == 0) red[wrp] = s2;
    __syncthreads();
    float var = (red[0] + red[1] + red[2] + red[3] + red[4] + red[5] + red[6] + red[7]) * (1.f / 256.f);
    g_Xs[(size_t)row * C_ + c] = d * rsqrtf(var + 1e-5f) * lnw[c] + lnb[c];
}

// ================= launch =====================================================
extern "C" void kernel_launch(void* const* d_in, const int* in_sizes, int n_in,
                              void* d_out, int out_size) {
    const float* x        = (const float*)d_in[0];
    const float* x_source = (const float*)d_in[1];
    const float* loc      = (const float*)d_in[2];
    const float* conf     = (const float*)d_in[3];
    const float* Wq       = (const float*)d_in[4];
    const float* Wk       = (const float*)d_in[5];
    const float* Wv       = (const float*)d_in[6];
    const float* sr_w     = (const float*)d_in[7];
    const float* sr_b     = (const float*)d_in[8];
    const float* ln_w     = (const float*)d_in[9];
    const float* ln_b     = (const float*)d_in[10];
    const float* Wp       = (const float*)d_in[11];
    const float* bp       = (const float*)d_in[12];
    float* out = (float*)d_out;

    float *pFmap, *pCnt, *pWkv, *pXs, *pAO;
    cudaGetSymbolAddress((void**)&pFmap, g_Fmap);
    cudaGetSymbolAddress((void**)&pCnt, g_Cnt);
    cudaGetSymbolAddress((void**)&pWkv, g_Wkv);
    cudaGetSymbolAddress((void**)&pXs, g_Xs);
    cudaGetSymbolAddress((void**)&pAO, g_AO);

    const size_t SM128 = 67584;
    const size_t SMATT = 20480 + 2 * (128 * 20 + 32 * 68 + 128) * 4;
    cudaFuncSetAttribute((const void*)conv_q_kernel,
                         cudaFuncAttributeMaxDynamicSharedMemorySize, (int)SM128);
    cudaFuncSetAttribute((const void*)gemm_kernel,
                         cudaFuncAttributeMaxDynamicSharedMemorySize, (int)SM128);
    cudaFuncSetAttribute((const void*)kv_gemm_kernel,
                         cudaFuncAttributeMaxDynamicSharedMemorySize, (int)SM128);
    cudaFuncSetAttribute((const void*)attn_fused,
                         cudaFuncAttributeMaxDynamicSharedMemorySize, (int)SMATT);

    // token2map
    cudaMemsetAsync(pFmap, 0, (size_t)B_ * HW_ * C_ * sizeof(float));
    cudaMemsetAsync(pCnt, 0, (size_t)B_ * HW_ * sizeof(float));
    scatter_kernel<<<(B_ * N_) / 8, 256>>>(x_source, loc);
    blur_fused_kernel<<<dim3(4, HM_, B_ * 4), 256>>>();

    // weight prep
    wprep_kernel<<<4096 + 512, 256>>>(sr_w, Wk, Wv);

    // conv (split-K x8, implicit im2col) + q projection, one launch (512 thr)
    conv_q_kernel<<<dim3(2, 144, 8), 512, SM128>>>(x, Wq);
    ln_kernel<<<B_ * NS_, 256>>>(sr_b, ln_w, ln_b);

    // fused k+v projection with packing epilogue
    kv_gemm_kernel<<<dim3(4, 16), 512, SM128>>>(pXs, pWkv);

    // fused attention
    attn_fused<<<dim3(N_ / 128, B_ * HEADS_), 256, SMATT>>>(conf);

    // output projection (+bias)
    gemm_kernel<<<dim3(2, 128), 512, SM128>>>(pAO, C_, Wp, C_, out, C_, C_, bp);
}

// round 15
// speedup vs baseline: 1.0580x; 1.0580x over previous
#include <cuda_runtime.h>
#include <cuda_fp16.h>
#include <cstdint>
#include <math.h>

// Problem constants
#define B_    2
#define N_    8192
#define C_    256
#define HEADS_ 8
#define DH_   32
#define HM_   128
#define HW_   (HM_*HM_)
#define NS_   1024
#define KCOL_ 4096
#define KSPL_ 8
#define KCH_  (KCOL_/KSPL_)   // 512

// ---------------- scratch (device globals) ------------------------------------
__device__ float g_Fmap[B_ * HW_ * C_];
__device__ float g_Cnt [B_ * HW_];
__device__ float g_Xm  [B_ * HW_ * C_];
__device__ float g_Wc  [C_ * KCOL_];
__device__ float g_Wkv [2 * C_ * C_];
__device__ float g_CPart[KSPL_ * B_ * NS_ * C_];
__device__ float g_Xs  [B_ * NS_ * C_];
__device__ float g_Q   [B_ * N_ * C_];
__device__ uint32_t g_KhW[16 * NS_ * 16];
__device__ uint32_t g_VtW[16 * 32 * 512];
__device__ float g_AO  [B_ * N_ * C_];

// ================= fp16 mma helpers ===========================================
__device__ __forceinline__ uint32_t pkh2(float a, float b) {
    __half2 h = __floats2half2_rn(a, b);
    return *(uint32_t*)&h;
}
__device__ __forceinline__ void f16split(float x, float& hi, float& lo) {
    float h = __half2float(__float2half_rn(x));
    hi = h; lo = x - h;
}
__device__ __forceinline__ void mma16(float* c, const uint32_t* a, const uint32_t* b) {
    asm volatile(
        "mma.sync.aligned.m16n8k16.row.col.f32.f16.f16.f32 "
        "{%0,%1,%2,%3}, {%4,%5,%6,%7}, {%8,%9}, {%0,%1,%2,%3};"
        : "+f"(c[0]), "+f"(c[1]), "+f"(c[2]), "+f"(c[3])
        : "r"(a[0]), "r"(a[1]), "r"(a[2]), "r"(a[3]), "r"(b[0]), "r"(b[1]));
}
__device__ __forceinline__ void ldsm_x4(uint32_t* d, uint32_t a) {
    asm volatile("ldmatrix.sync.aligned.m8n8.x4.shared.b16 {%0,%1,%2,%3}, [%4];"
                 : "=r"(d[0]), "=r"(d[1]), "=r"(d[2]), "=r"(d[3]) : "r"(a));
}
__device__ __forceinline__ void ldsm_x2(uint32_t* d, uint32_t a) {
    asm volatile("ldmatrix.sync.aligned.m8n8.x2.shared.b16 {%0,%1}, [%2];"
                 : "=r"(d[0]), "=r"(d[1]) : "r"(a));
}
__device__ __forceinline__ uint32_t s2u(const void* p) {
    return (uint32_t)__cvta_generic_to_shared(p);
}

// implicit-im2col address for conv A
__device__ __forceinline__ const float* convA_addr(int m, int k) {
    int b = m >> 10, rr = m & 1023;
    int oy = rr >> 5, ox = rr & 31;
    int kk = k >> 8, ci = k & 255;
    int ky = kk >> 2, kx = kk & 3;
    int pix = (b << 14) + (oy * 4 + ky) * HM_ + ox * 4 + kx;
    return g_Xm + (size_t)pix * 256 + ci;
}

// ================= asymmetric fp16 GEMM body (R13 + ldmatrix) =================
// EPI 0: C = A@B^T (+bias).  EPI 2: kv-pack epilogue.
template<int BN, int WARPS_M, int WARPS_N, bool CONVA, int EPI>
__device__ __forceinline__ void gemm_body(
        const float* __restrict__ A, int lda, int kbase,
        const float* __restrict__ Bw, int ldb,
        float* __restrict__ Cb, int ldc,
        int K, const float* __restrict__ bias, int n0, int m0) {
    constexpr int WM_T = 128 / WARPS_M / 16;
    constexpr int WN_T = BN / WARPS_N / 8;
    constexpr int NB4 = BN / 32;
    constexpr int ES = BN + 4;
    constexpr int STW = 128 * 20 * 2 + BN * 20;

    extern __shared__ float smem[];
    uint32_t* stage0 = (uint32_t*)smem;
    float* epi = smem;

    const int t = threadIdx.x, lane = t & 31, warp = t >> 5;
    const int g = lane >> 2, tig = lane & 3;
    const int warpM = warp / WARPS_N, warpN = warp % WARPS_N;
    const int wrb = warpM * WM_T * 16, wcb = warpN * WN_T * 8;

    // ldmatrix lane geometry (verified correct in R10)
    const int lrow = (lane & 7) | (((lane >> 3) & 1) << 3);
    const int lwof4 = (lane >> 4) << 2;
    const int browb = lane & 7;
    const int bwof4 = ((lane >> 3) & 1) << 2;

    const int lr = t >> 3;
    const int lc = (t & 7) * 4;

    float acc[WM_T][WN_T][4];
#pragma unroll
    for (int i = 0; i < WM_T; i++)
#pragma unroll
        for (int j = 0; j < WN_T; j++)
#pragma unroll
            for (int q = 0; q < 4; q++) acc[i][j][q] = 0.f;

    const int nc = K >> 5;
    float4 pa[4], pb[NB4];

#define GB_LOAD(cc_)                                                              \
    {                                                                             \
        int k0_ = (cc_) << 5;                                                     \
        _Pragma("unroll")                                                         \
        for (int i = 0; i < 4; i++) {                                             \
            if (CONVA)                                                            \
                pa[i] = *(const float4*)convA_addr(m0 + lr + i * 32, kbase + k0_ + lc); \
            else                                                                  \
                pa[i] = *(const float4*)(A + (size_t)(m0 + lr + i * 32) * lda + k0_ + lc); \
        }                                                                         \
        _Pragma("unroll")                                                         \
        for (int i = 0; i < NB4; i++)                                             \
            pb[i] = *(const float4*)(Bw + (size_t)(n0 + lr + i * 32) * ldb + kbase + k0_ + lc); \
    }

#define GB_STORE(st_)                                                             \
    {                                                                             \
        uint32_t* AshW_ = stage0 + (st_) * STW;                                   \
        uint32_t* AslW_ = AshW_ + 128 * 20;                                       \
        uint32_t* BshW_ = AslW_ + 128 * 20;                                       \
        _Pragma("unroll")                                                         \
        for (int i = 0; i < 4; i++) {                                             \
            float h0, l0, h1, l1, h2, l2, h3, l3;                                 \
            f16split(pa[i].x, h0, l0); f16split(pa[i].y, h1, l1);                 \
            f16split(pa[i].z, h2, l2); f16split(pa[i].w, h3, l3);                 \
            *(uint2*)&AshW_[(lr + i * 32) * 20 + (lc >> 1)] = make_uint2(pkh2(h0, h1), pkh2(h2, h3)); \
            *(uint2*)&AslW_[(lr + i * 32) * 20 + (lc >> 1)] = make_uint2(pkh2(l0, l1), pkh2(l2, l3)); \
        }                                                                         \
        _Pragma("unroll")                                                         \
        for (int i = 0; i < NB4; i++)                                             \
            *(uint2*)&BshW_[(lr + i * 32) * 20 + (lc >> 1)] =                     \
                make_uint2(pkh2(pb[i].x, pb[i].y), pkh2(pb[i].z, pb[i].w));       \
    }

    GB_LOAD(0);
    GB_STORE(0);
    __syncthreads();
    if (nc > 1) GB_LOAD(1);

    for (int c = 0; c < nc; c++) {
        const int st = c & 1;
        uint32_t* AshW = stage0 + st * STW;
        const uint32_t a_h = s2u(AshW);
        const uint32_t a_l = a_h + 128 * 20 * 4;
        const uint32_t b_b = a_l + 128 * 20 * 4;
#pragma unroll
        for (int ks = 0; ks < 2; ks++) {
            const int w0 = ks * 8;
            uint32_t ah[WM_T][4], al[WM_T][4];
#pragma unroll
            for (int mt = 0; mt < WM_T; mt++) {
                uint32_t aoff = (uint32_t)(((wrb + mt * 16 + lrow) * 20 + w0 + lwof4) * 4);
                ldsm_x4(ah[mt], a_h + aoff);
                ldsm_x4(al[mt], a_l + aoff);
            }
            uint32_t bh[WN_T][2];
#pragma unroll
            for (int nt = 0; nt < WN_T; nt++) {
                uint32_t boff = (uint32_t)(((wcb + nt * 8 + browb) * 20 + w0 + bwof4) * 4);
                ldsm_x2(bh[nt], b_b + boff);
            }
#pragma unroll
            for (int mt = 0; mt < WM_T; mt++)
#pragma unroll
                for (int nt = 0; nt < WN_T; nt++) {
                    mma16(acc[mt][nt], ah[mt], bh[nt]);
                    mma16(acc[mt][nt], al[mt], bh[nt]);
                }
        }
        if (c + 1 < nc) {
            GB_STORE(st ^ 1);
            __syncthreads();
            if (c + 2 < nc) GB_LOAD(c + 2);
        }
    }
    __syncthreads();
#pragma unroll
    for (int mt = 0; mt < WM_T; mt++)
#pragma unroll
        for (int nt = 0; nt < WN_T; nt++) {
            int r = wrb + mt * 16 + g;
            int cc = wcb + nt * 8 + 2 * tig;
            epi[r * ES + cc] = acc[mt][nt][0];
            epi[r * ES + cc + 1] = acc[mt][nt][1];
            epi[(r + 8) * ES + cc] = acc[mt][nt][2];
            epi[(r + 8) * ES + cc + 1] = acc[mt][nt][3];
        }
    __syncthreads();

    if (EPI == 0) {
        for (int idx = t; idx < 128 * BN; idx += 256) {
            int r = idx / BN, cc = idx % BN;
            float v = epi[r * ES + cc];
            if (bias) v += bias[n0 + cc];
            Cb[(size_t)(m0 + r) * ldc + n0 + cc] = v;
        }
    } else {
        if (n0 < 256) {
            for (int u = t; u < 128 * 64; u += 256) {
                int r = u >> 6, wp = u & 63;
                int cc = 2 * wp;
                int dim = n0 + cc;
                int h = dim >> 5, w2 = (dim & 31) >> 1;
                int m = m0 + r;
                int b = m >> 10, key = m & 1023;
                g_KhW[((size_t)((b * 8 + h) * NS_ + key)) * 16 + w2] =
                    pkh2(epi[r * ES + cc], epi[r * ES + cc + 1]);
            }
        } else {
            for (int u = t; u < 64 * 128; u += 256) {
                int wl = u >> 7, cc = u & 127;
                int dim = n0 - 256 + cc;
                int h = dim >> 5, d = dim & 31;
                int m = m0 + 2 * wl;
                int b = m >> 10, keyloc = m & 1023;
                g_VtW[((size_t)((b * 8 + h) * 32 + d)) * 512 + (keyloc >> 1)] =
                    pkh2(epi[(2 * wl) * ES + cc], epi[(2 * wl + 1) * ES + cc]);
            }
        }
    }
#undef GB_LOAD
#undef GB_STORE
}

// ---- merged conv(split-K x8) + q-projection launch ----------------------------
__global__ void __launch_bounds__(256, 1)
conv_q_kernel(const float* __restrict__ x, const float* __restrict__ Wq) {
    if (blockIdx.y < 16) {
        int zh = blockIdx.z;
        gemm_body<128, 2, 4, true, 0>(
            nullptr, 0, zh * KCH_, g_Wc, KCOL_,
            g_CPart + (size_t)zh * (B_ * NS_ * C_), C_,
            KCH_, nullptr, blockIdx.x * 128, blockIdx.y * 128);
    } else {
        if (blockIdx.z) return;
        gemm_body<128, 2, 4, false, 0>(
            x, C_, 0, Wq, C_, g_Q, C_,
            C_, nullptr, blockIdx.x * 128, (blockIdx.y - 16) * 128);
    }
}

__global__ void __launch_bounds__(256, 1)
gemm_kernel(const float* __restrict__ A, int lda,
            const float* __restrict__ Bw, int ldb,
            float* __restrict__ Cm, int ldc,
            int K, const float* __restrict__ bias) {
    gemm_body<128, 2, 4, false, 0>(A, lda, 0, Bw, ldb, Cm, ldc, K, bias,
                                   blockIdx.x * 128, blockIdx.y * 128);
}

__global__ void __launch_bounds__(256, 1)
kv_gemm_kernel(const float* __restrict__ A, const float* __restrict__ Bw) {
    gemm_body<128, 2, 4, false, 2>(A, C_, 0, Bw, C_, nullptr, 0, C_, nullptr,
                                   blockIdx.x * 128, blockIdx.y * 128);
}

// ================= fused flash attention (R13 + ldmatrix) =====================
__global__ void __launch_bounds__(256, 2)
attn_fused(const float* __restrict__ conf) {
    extern __shared__ float smem[];
    uint32_t* QhW = (uint32_t*)smem;            // [128][20]
    uint32_t* QlW = QhW + 128 * 20;
    uint32_t* stg = QlW + 128 * 20;             // 2 stages: [128*20 K][32*68 V][128 conf]
    const int STW = 128 * 20 + 32 * 68 + 128;

    const int t = threadIdx.x, lane = t & 31, warp = t >> 5;
    const int g = lane >> 2, tig = lane & 3;
    const int bh = blockIdx.y, b = bh >> 3, h = bh & 7;
    const int m0 = blockIdx.x << 7;
    const int wrb = warp << 4;
    const float scale = 0.17677669529663687f;

    const int lrow = (lane & 7) | (((lane >> 3) & 1) << 3);
    const int lwof4 = (lane >> 4) << 2;
    const int browb = lane & 7;
    const int bwof4 = ((lane >> 3) & 1) << 2;

    {
        const int lr = t >> 3, lc = (t & 7) * 4;
#pragma unroll
        for (int i = 0; i < 4; i++) {
            int r = lr + i * 32;
            float4 v = *(const float4*)(g_Q + (size_t)(b * N_ + m0 + r) * C_ + h * DH_ + lc);
            float h0, l0, h1, l1, h2, l2, h3, l3;
            f16split(v.x * scale, h0, l0); f16split(v.y * scale, h1, l1);
            f16split(v.z * scale, h2, l2); f16split(v.w * scale, h3, l3);
            *(uint2*)&QhW[r * 20 + (lc >> 1)] = make_uint2(pkh2(h0, h1), pkh2(h2, h3));
            *(uint2*)&QlW[r * 20 + (lc >> 1)] = make_uint2(pkh2(l0, l1), pkh2(l2, l3));
        }
    }

    float Oacc[4][4];
#pragma unroll
    for (int i = 0; i < 4; i++)
#pragma unroll
        for (int j = 0; j < 4; j++) Oacc[i][j] = 0.f;
    float l0s = 0.f, l1s = 0.f;

    const uint4* KhG = (const uint4*)g_KhW;
    const uint4* VtG = (const uint4*)g_VtW;
    uint4 kr[2], vr[2];
    float cf;

#define AT_LOAD(kc_)                                                              \
    {                                                                             \
        int kb_ = (kc_) << 7;                                                     \
        _Pragma("unroll")                                                         \
        for (int i = 0; i < 2; i++) {                                             \
            int u = t + i * 256;                                                  \
            kr[i] = KhG[(size_t)(bh * NS_ + kb_ + (u >> 2)) * 4 + (u & 3)];       \
            vr[i] = VtG[(size_t)(bh * 32 + (u >> 4)) * 128 + (kc_) * 16 + (u & 15)]; \
        }                                                                         \
        if (t < 128) cf = conf[b * NS_ + kb_ + t];                                \
    }

#define AT_STORE(st_)                                                             \
    {                                                                             \
        uint32_t* KsW_ = stg + (st_) * STW;                                       \
        uint32_t* VsW_ = KsW_ + 128 * 20;                                         \
        float* cf_ = (float*)(VsW_ + 32 * 68);                                    \
        _Pragma("unroll")                                                         \
        for (int i = 0; i < 2; i++) {                                             \
            int u = t + i * 256;                                                  \
            *(uint4*)&KsW_[(u >> 2) * 20 + 4 * (u & 3)] = kr[i];                  \
            *(uint4*)&VsW_[(u >> 4) * 68 + 4 * (u & 15)] = vr[i];                 \
        }                                                                         \
        if (t < 128) cf_[t] = cf;                                                 \
    }

    AT_LOAD(0);
    AT_STORE(0);
    __syncthreads();
    AT_LOAD(1);

    const uint32_t qh_b = s2u(QhW);
    const uint32_t ql_b = s2u(QlW);

    for (int kc = 0; kc < 8; kc++) {
        const int st = kc & 1;
        uint32_t* KsW = stg + st * STW;
        uint32_t* VsW = KsW + 128 * 20;
        const float* confs = (const float*)(VsW + 32 * 68);
        const uint32_t k_b = s2u(KsW);
        const uint32_t v_b = s2u(VsW);

#pragma unroll
        for (int h2 = 0; h2 < 2; h2++) {
            float Sacc[8][4];
#pragma unroll
            for (int nt = 0; nt < 8; nt++)
#pragma unroll
                for (int q = 0; q < 4; q++) Sacc[nt][q] = 0.f;

#pragma unroll
            for (int ks = 0; ks < 2; ks++) {
                const int w0 = ks * 8;
                uint32_t ah[4], al[4];
                uint32_t aoff = (uint32_t)(((wrb + lrow) * 20 + w0 + lwof4) * 4);
                ldsm_x4(ah, qh_b + aoff);
                ldsm_x4(al, ql_b + aoff);
#pragma unroll
                for (int nt = 0; nt < 8; nt++) {
                    uint32_t bv[2];
                    uint32_t boff = (uint32_t)((((h2 * 8 + nt) * 8 + browb) * 20 + w0 + bwof4) * 4);
                    ldsm_x2(bv, k_b + boff);
                    mma16(Sacc[nt], ah, bv);
                    mma16(Sacc[nt], al, bv);
                }
            }

#pragma unroll
            for (int jj = 0; jj < 4; jj++) {
                const int j = h2 * 4 + jj;
                const int nt0 = 2 * jj, nt1 = 2 * jj + 1;
                const int ng0 = h2 * 8 + nt0, ng1 = h2 * 8 + nt1;
                float ca0 = confs[ng0 * 8 + 2 * tig], cb0 = confs[ng0 * 8 + 2 * tig + 1];
                float ca1 = confs[ng1 * 8 + 2 * tig], cb1 = confs[ng1 * 8 + 2 * tig + 1];
                float p00 = __expf(Sacc[nt0][0] + ca0);
                float p01 = __expf(Sacc[nt0][1] + cb0);
                float p02 = __expf(Sacc[nt0][2] + ca0);
                float p03 = __expf(Sacc[nt0][3] + cb0);
                float p10 = __expf(Sacc[nt1][0] + ca1);
                float p11 = __expf(Sacc[nt1][1] + cb1);
                float p12 = __expf(Sacc[nt1][2] + ca1);
                float p13 = __expf(Sacc[nt1][3] + cb1);
                l0s += p00 + p01 + p10 + p11;
                l1s += p02 + p03 + p12 + p13;

                uint32_t a[4];
                a[0] = pkh2(p00, p01);
                a[1] = pkh2(p02, p03);
                a[2] = pkh2(p10, p11);
                a[3] = pkh2(p12, p13);
#pragma unroll
                for (int dt = 0; dt < 4; dt++) {
                    uint32_t bv[2];
                    uint32_t boff = (uint32_t)(((dt * 8 + browb) * 68 + 8 * j + bwof4) * 4);
                    ldsm_x2(bv, v_b + boff);
                    mma16(Oacc[dt], a, bv);
                }
            }
        }

        if (kc + 1 < 8) {
            AT_STORE(st ^ 1);
            __syncthreads();
            if (kc + 2 < 8) AT_LOAD(kc + 2);
        }
    }
#undef AT_LOAD
#undef AT_STORE

    l0s += __shfl_xor_sync(~0u, l0s, 1); l0s += __shfl_xor_sync(~0u, l0s, 2);
    l1s += __shfl_xor_sync(~0u, l1s, 1); l1s += __shfl_xor_sync(~0u, l1s, 2);
    float r0inv = 1.f / l0s, r1inv = 1.f / l1s;

#pragma unroll
    for (int dt = 0; dt < 4; dt++) {
        int cc = h * DH_ + dt * 8 + 2 * tig;
        size_t rowa = (size_t)(b * N_ + m0 + wrb + g) * C_;
        size_t rowb = (size_t)(b * N_ + m0 + wrb + 8 + g) * C_;
        g_AO[rowa + cc]     = Oacc[dt][0] * r0inv;
        g_AO[rowa + cc + 1] = Oacc[dt][1] * r0inv;
        g_AO[rowb + cc]     = Oacc[dt][2] * r1inv;
        g_AO[rowb + cc + 1] = Oacc[dt][3] * r1inv;
    }
}

// ================= preprocessing ==============================================
__global__ void __launch_bounds__(256) scatter_kernel(const float* __restrict__ xs,
                                                      const float* __restrict__ loc) {
    const int tok0 = blockIdx.x << 3;
    const int c = threadIdx.x;
    int p[8];
#pragma unroll
    for (int i = 0; i < 8; i++) {
        int token = tok0 + i;
        int b = token >> 13;
        float lx = loc[(size_t)token * 2 + 0];
        float ly = loc[(size_t)token * 2 + 1];
        lx = fminf(fmaxf(lx, 0.f), 1.f) * 127.f;
        ly = fminf(fmaxf(ly, 0.f), 1.f) * 127.f;
        p[i] = (b << 14) + (int)rintf(ly) * HM_ + (int)rintf(lx);
    }
#pragma unroll
    for (int i = 0; i < 8; i++) {
        atomicAdd(&g_Fmap[(size_t)p[i] * C_ + c], xs[(size_t)(tok0 + i) * C_ + c]);
        if (c == 0) atomicAdd(&g_Cnt[p[i]], 1.0f);
    }
}

__global__ void __launch_bounds__(256) blur_fused_kernel() {
    __shared__ float sf[3][34][64];
    __shared__ float minv[3][34];
    __shared__ float msk[3][34];

    const int t = threadIdx.x;
    const int x0 = blockIdx.x << 5;
    const int y = blockIdx.y;
    const int b = blockIdx.z >> 2, cg = blockIdx.z & 3;
    const int cbase = cg << 6;

    if (t < 102) {
        int r = t / 34, px = t % 34;
        int gy = y + r - 1, gx = x0 + px - 1;
        float inv = 0.f, mk = 0.f;
        if (gy >= 0 && gy < HM_ && gx >= 0 && gx < HM_) {
            float cnt = g_Cnt[(b << 14) + gy * HM_ + gx];
            if (cnt > 0.f) { inv = 1.f / (cnt + 1e-6f); mk = 1.f; }
        }
        minv[r][px] = inv;
        msk[r][px] = mk;
    }
    __syncthreads();

    for (int idx = t; idx < 3 * 34 * 64; idx += 256) {
        int r = idx / (34 * 64);
        int rem = idx - r * (34 * 64);
        int px = rem >> 6, c = rem & 63;
        int gy = y + r - 1, gx = x0 + px - 1;
        float val = 0.f;
        if (gy >= 0 && gy < HM_ && gx >= 0 && gx < HM_) {
            int pix = (b << 14) + gy * HM_ + gx;
            val = g_Fmap[(size_t)pix * 256 + cbase + c] * minv[r][px];
        }
        sf[r][px][c] = val;
    }
    __syncthreads();

    const float e1 = 0.88249690258459546f;
    const float e2 = 0.77880078307140487f;
    const float nrm = 1.0f / (1.0f + 4.0f * e1 + 4.0f * e2);
    const float wc = nrm, we = e1 * nrm, wo = e2 * nrm;

    const int c = t & 63;
    const int pg = t >> 6;
#pragma unroll
    for (int i = 0; i < 8; i++) {
        int px = pg * 8 + i;
        int ps = px + 1;
        float msum =
            wo * (msk[0][ps - 1] + msk[0][ps + 1] + msk[2][ps - 1] + msk[2][ps + 1]) +
            we * (msk[0][ps] + msk[1][ps - 1] + msk[1][ps + 1] + msk[2][ps]) +
            wc * msk[1][ps];
        float fsum =
            wo * (sf[0][ps - 1][c] + sf[0][ps + 1][c] + sf[2][ps - 1][c] + sf[2][ps + 1][c]) +
            we * (sf[0][ps][c] + sf[1][ps - 1][c] + sf[1][ps + 1][c] + sf[2][ps][c]) +
            wc * sf[1][ps][c];
        float fint = (msum > 0.f) ? fsum / (msum + 1e-6f) : 0.f;
        float fc = sf[1][ps][c];
        float mc = msk[1][ps];
        int cp = (b << 14) + y * HM_ + x0 + px;
        g_Xm[(size_t)cp * 256 + cbase + c] = fc + (1.f - mc) * fint;
    }
}

__global__ void __launch_bounds__(256) wprep_kernel(const float* __restrict__ srw,
                                                    const float* __restrict__ Wk,
                                                    const float* __restrict__ Wv) {
    int blk = blockIdx.x;
    if (blk < 4096) {
        int idx = blk * 256 + threadIdx.x;
        int co = idx >> 12;
        int r = idx & 4095;
        int kk = r >> 8;
        int ci = r & 255;
        g_Wc[idx] = srw[(size_t)co * 4096 + ci * 16 + kk];
    } else {
        int idx = (blk - 4096) * 256 + threadIdx.x;
        int row = idx >> 8, c = idx & 255;
        g_Wkv[idx] = (row < 256) ? Wk[row * 256 + c] : Wv[(row - 256) * 256 + c];
    }
}

__global__ void __launch_bounds__(256) ln_kernel(const float* __restrict__ srb,
                                                 const float* __restrict__ lnw,
                                                 const float* __restrict__ lnb) {
    __shared__ float red[8];
    int row = blockIdx.x, c = threadIdx.x;
    int lane = c & 31, wrp = c >> 5;
    float v = srb[c];
#pragma unroll
    for (int s = 0; s < KSPL_; s++)
        v += g_CPart[(size_t)s * (B_ * NS_ * C_) + (size_t)row * C_ + c];
    float s = v;
#pragma unroll
    for (int o = 16; o; o >>= 1) s += __shfl_xor_sync(~0u, s, o);
    if (lane == 0) red[wrp] = s;
    __syncthreads();
    float mu = (red[0] + red[1] + red[2] + red[3] + red[4] + red[5] + red[6] + red[7]) * (1.f / 256.f);
    float d = v - mu;
    float s2 = d * d;
#pragma unroll
    for (int o = 16; o; o >>= 1) s2 += __shfl_xor_sync(~0u, s2, o);
    __syncthreads();
    if (lane == 0) red[wrp] = s2;
    __syncthreads();
    float var = (red[0] + red[1] + red[2] + red[3] + red[4] + red[5] + red[6] + red[7]) * (1.f / 256.f);
    g_Xs[(size_t)row * C_ + c] = d * rsqrtf(var + 1e-5f) * lnw[c] + lnb[c];
}

// ================= launch =====================================================
extern "C" void kernel_launch(void* const* d_in, const int* in_sizes, int n_in,
                              void* d_out, int out_size) {
    const float* x        = (const float*)d_in[0];
    const float* x_source = (const float*)d_in[1];
    const float* loc      = (const float*)d_in[2];
    const float* conf     = (const float*)d_in[3];
    const float* Wq       = (const float*)d_in[4];
    const float* Wk       = (const float*)d_in[5];
    const float* Wv       = (const float*)d_in[6];
    const float* sr_w     = (const float*)d_in[7];
    const float* sr_b     = (const float*)d_in[8];
    const float* ln_w     = (const float*)d_in[9];
    const float* ln_b     = (const float*)d_in[10];
    const float* Wp       = (const float*)d_in[11];
    const float* bp       = (const float*)d_in[12];
    float* out = (float*)d_out;

    float *pFmap, *pCnt, *pWkv, *pXs, *pAO;
    cudaGetSymbolAddress((void**)&pFmap, g_Fmap);
    cudaGetSymbolAddress((void**)&pCnt, g_Cnt);
    cudaGetSymbolAddress((void**)&pWkv, g_Wkv);
    cudaGetSymbolAddress((void**)&pXs, g_Xs);
    cudaGetSymbolAddress((void**)&pAO, g_AO);

    const size_t SM128 = 67584;
    const size_t SMATT = 20480 + 2 * (128 * 20 + 32 * 68 + 128) * 4;
    cudaFuncSetAttribute((const void*)conv_q_kernel,
                         cudaFuncAttributeMaxDynamicSharedMemorySize, (int)SM128);
    cudaFuncSetAttribute((const void*)gemm_kernel,
                         cudaFuncAttributeMaxDynamicSharedMemorySize, (int)SM128);
    cudaFuncSetAttribute((const void*)kv_gemm_kernel,
                         cudaFuncAttributeMaxDynamicSharedMemorySize, (int)SM128);
    cudaFuncSetAttribute((const void*)attn_fused,
                         cudaFuncAttributeMaxDynamicSharedMemorySize, (int)SMATT);

    // token2map
    cudaMemsetAsync(pFmap, 0, (size_t)B_ * HW_ * C_ * sizeof(float));
    cudaMemsetAsync(pCnt, 0, (size_t)B_ * HW_ * sizeof(float));
    scatter_kernel<<<(B_ * N_) / 8, 256>>>(x_source, loc);
    blur_fused_kernel<<<dim3(4, HM_, B_ * 4), 256>>>();

    // weight prep
    wprep_kernel<<<4096 + 512, 256>>>(sr_w, Wk, Wv);

    // conv (split-K x8, implicit im2col) + q projection, one launch
    conv_q_kernel<<<dim3(2, 144, 8), 256, SM128>>>(x, Wq);
    ln_kernel<<<B_ * NS_, 256>>>(sr_b, ln_w, ln_b);

    // fused k+v projection with packing epilogue
    kv_gemm_kernel<<<dim3(4, 16), 256, SM128>>>(pXs, pWkv);

    // fused attention
    attn_fused<<<dim3(N_ / 128, B_ * HEADS_), 256, SMATT>>>(conf);

    // output projection (+bias)
    gemm_kernel<<<dim3(2, 128), 256, SM128>>>(pAO, C_, Wp, C_, out, C_, C_, bp);
}

// round 16
// speedup vs baseline: 1.0733x; 1.0145x over previous
#include <cuda_runtime.h>
#include <cuda_fp16.h>
#include <cstdint>
#include <math.h>

// Problem constants
#define B_    2
#define N_    8192
#define C_    256
#define HEADS_ 8
#define DH_   32
#define HM_   128
#define HW_   (HM_*HM_)
#define NS_   1024
#define KCOL_ 4096
#define KSPL_ 4
#define KCH_  (KCOL_/KSPL_)   // 1024

// ---------------- scratch (device globals) ------------------------------------
__device__ float    g_Fmap[B_ * HW_ * C_];
__device__ float    g_Cnt [B_ * HW_];
__device__ float    g_Xm  [B_ * HW_ * C_];
__device__ uint32_t g_WcP [C_ * (KCOL_ / 2)];     // permuted conv weights, f16 words
__device__ uint32_t g_WkvP[512 * 128];            // [Wk;Wv] f16 words
__device__ uint32_t g_WqP [256 * 128];
__device__ uint32_t g_WpP [256 * 128];
__device__ float    g_CPart[KSPL_ * B_ * NS_ * C_];
__device__ float    g_Xs  [B_ * NS_ * C_];
__device__ float    g_Q   [B_ * N_ * C_];
__device__ uint32_t g_KhW [16 * NS_ * 16];
__device__ uint32_t g_VtW [16 * 32 * 512];
__device__ float    g_AO  [B_ * N_ * C_];

// ================= fp16 mma helpers ===========================================
__device__ __forceinline__ uint32_t pkh2(float a, float b) {
    __half2 h = __floats2half2_rn(a, b);
    return *(uint32_t*)&h;
}
__device__ __forceinline__ void f16split(float x, float& hi, float& lo) {
    float h = __half2float(__float2half_rn(x));
    hi = h; lo = x - h;
}
__device__ __forceinline__ void mma16(float* c, const uint32_t* a, const uint32_t* b) {
    asm volatile(
        "mma.sync.aligned.m16n8k16.row.col.f32.f16.f16.f32 "
        "{%0,%1,%2,%3}, {%4,%5,%6,%7}, {%8,%9}, {%0,%1,%2,%3};"
        : "+f"(c[0]), "+f"(c[1]), "+f"(c[2]), "+f"(c[3])
        : "r"(a[0]), "r"(a[1]), "r"(a[2]), "r"(a[3]), "r"(b[0]), "r"(b[1]));
}
__device__ __forceinline__ void ldsm_x4(uint32_t* d, uint32_t a) {
    asm volatile("ldmatrix.sync.aligned.m8n8.x4.shared.b16 {%0,%1,%2,%3}, [%4];"
                 : "=r"(d[0]), "=r"(d[1]), "=r"(d[2]), "=r"(d[3]) : "r"(a));
}
__device__ __forceinline__ void ldsm_x2(uint32_t* d, uint32_t a) {
    asm volatile("ldmatrix.sync.aligned.m8n8.x2.shared.b16 {%0,%1}, [%2];"
                 : "=r"(d[0]), "=r"(d[1]) : "r"(a));
}
__device__ __forceinline__ uint32_t s2u(const void* p) {
    return (uint32_t)__cvta_generic_to_shared(p);
}

// implicit-im2col address for conv A
__device__ __forceinline__ const float* convA_addr(int m, int k) {
    int b = m >> 10, rr = m & 1023;
    int oy = rr >> 5, ox = rr & 31;
    int kk = k >> 8, ci = k & 255;
    int ky = kk >> 2, kx = kk & 3;
    int pix = (b << 14) + (oy * 4 + ky) * HM_ + ox * 4 + kx;
    return g_Xm + (size_t)pix * 256 + ci;
}

// ================= asymmetric fp16 GEMM body (B pre-packed fp16) ==============
// EPI 0: C = A@B^T (+bias).  EPI 2: kv-pack epilogue.
template<int BN, int WARPS_M, int WARPS_N, bool CONVA, int EPI>
__device__ __forceinline__ void gemm_body(
        const float* __restrict__ A, int lda, int kbase,
        const uint32_t* __restrict__ BwP, int ldbW,
        float* __restrict__ Cb, int ldc,
        int K, const float* __restrict__ bias, int n0, int m0) {
    constexpr int WM_T = 128 / WARPS_M / 16;
    constexpr int WN_T = BN / WARPS_N / 8;
    constexpr int NB4 = BN / 32;
    constexpr int ES = BN + 4;
    constexpr int STW = 128 * 20 * 2 + BN * 20;

    extern __shared__ float smem[];
    uint32_t* stage0 = (uint32_t*)smem;
    float* epi = smem;

    const int t = threadIdx.x, lane = t & 31, warp = t >> 5;
    const int g = lane >> 2, tig = lane & 3;
    const int warpM = warp / WARPS_N, warpN = warp % WARPS_N;
    const int wrb = warpM * WM_T * 16, wcb = warpN * WN_T * 8;

    // ldmatrix lane geometry
    const int lrow = (lane & 7) | (((lane >> 3) & 1) << 3);
    const int lwof4 = (lane >> 4) << 2;
    const int browb = lane & 7;
    const int bwof4 = ((lane >> 3) & 1) << 2;

    const int lr = t >> 3;
    const int lc = (t & 7) * 4;

    float acc[WM_T][WN_T][4];
#pragma unroll
    for (int i = 0; i < WM_T; i++)
#pragma unroll
        for (int j = 0; j < WN_T; j++)
#pragma unroll
            for (int q = 0; q < 4; q++) acc[i][j][q] = 0.f;

    const int nc = K >> 5;
    float4 pa[4];
    uint2 pbW[NB4];

#define GB_LOAD(cc_)                                                              \
    {                                                                             \
        int k0_ = (cc_) << 5;                                                     \
        _Pragma("unroll")                                                         \
        for (int i = 0; i < 4; i++) {                                             \
            if (CONVA)                                                            \
                pa[i] = *(const float4*)convA_addr(m0 + lr + i * 32, kbase + k0_ + lc); \
            else                                                                  \
                pa[i] = *(const float4*)(A + (size_t)(m0 + lr + i * 32) * lda + k0_ + lc); \
        }                                                                         \
        _Pragma("unroll")                                                         \
        for (int i = 0; i < NB4; i++)                                             \
            pbW[i] = *(const uint2*)(BwP + (size_t)(n0 + lr + i * 32) * ldbW +    \
                                     ((kbase + k0_) >> 1) + (lc >> 1));           \
    }

#define GB_STORE(st_)                                                             \
    {                                                                             \
        uint32_t* AshW_ = stage0 + (st_) * STW;                                   \
        uint32_t* AslW_ = AshW_ + 128 * 20;                                       \
        uint32_t* BshW_ = AslW_ + 128 * 20;                                       \
        _Pragma("unroll")                                                         \
        for (int i = 0; i < 4; i++) {                                             \
            float h0, l0, h1, l1, h2, l2, h3, l3;                                 \
            f16split(pa[i].x, h0, l0); f16split(pa[i].y, h1, l1);                 \
            f16split(pa[i].z, h2, l2); f16split(pa[i].w, h3, l3);                 \
            *(uint2*)&AshW_[(lr + i * 32) * 20 + (lc >> 1)] = make_uint2(pkh2(h0, h1), pkh2(h2, h3)); \
            *(uint2*)&AslW_[(lr + i * 32) * 20 + (lc >> 1)] = make_uint2(pkh2(l0, l1), pkh2(l2, l3)); \
        }                                                                         \
        _Pragma("unroll")                                                         \
        for (int i = 0; i < NB4; i++)                                             \
            *(uint2*)&BshW_[(lr + i * 32) * 20 + (lc >> 1)] = pbW[i];             \
    }

    GB_LOAD(0);
    GB_STORE(0);
    __syncthreads();
    if (nc > 1) GB_LOAD(1);

    for (int c = 0; c < nc; c++) {
        const int st = c & 1;
        uint32_t* AshW = stage0 + st * STW;
        const uint32_t a_h = s2u(AshW);
        const uint32_t a_l = a_h + 128 * 20 * 4;
        const uint32_t b_b = a_l + 128 * 20 * 4;
#pragma unroll
        for (int ks = 0; ks < 2; ks++) {
            const int w0 = ks * 8;
            uint32_t ah[WM_T][4], al[WM_T][4];
#pragma unroll
            for (int mt = 0; mt < WM_T; mt++) {
                uint32_t aoff = (uint32_t)(((wrb + mt * 16 + lrow) * 20 + w0 + lwof4) * 4);
                ldsm_x4(ah[mt], a_h + aoff);
                ldsm_x4(al[mt], a_l + aoff);
            }
            uint32_t bh[WN_T][2];
#pragma unroll
            for (int nt = 0; nt < WN_T; nt++) {
                uint32_t boff = (uint32_t)(((wcb + nt * 8 + browb) * 20 + w0 + bwof4) * 4);
                ldsm_x2(bh[nt], b_b + boff);
            }
#pragma unroll
            for (int mt = 0; mt < WM_T; mt++)
#pragma unroll
                for (int nt = 0; nt < WN_T; nt++) {
                    mma16(acc[mt][nt], ah[mt], bh[nt]);
                    mma16(acc[mt][nt], al[mt], bh[nt]);
                }
        }
        if (c + 1 < nc) {
            GB_STORE(st ^ 1);
            __syncthreads();
            if (c + 2 < nc) GB_LOAD(c + 2);
        }
    }
    __syncthreads();
#pragma unroll
    for (int mt = 0; mt < WM_T; mt++)
#pragma unroll
        for (int nt = 0; nt < WN_T; nt++) {
            int r = wrb + mt * 16 + g;
            int cc = wcb + nt * 8 + 2 * tig;
            epi[r * ES + cc] = acc[mt][nt][0];
            epi[r * ES + cc + 1] = acc[mt][nt][1];
            epi[(r + 8) * ES + cc] = acc[mt][nt][2];
            epi[(r + 8) * ES + cc + 1] = acc[mt][nt][3];
        }
    __syncthreads();

    if (EPI == 0) {
        for (int idx = t; idx < 128 * BN; idx += 256) {
            int r = idx / BN, cc = idx % BN;
            float v = epi[r * ES + cc];
            if (bias) v += bias[n0 + cc];
            Cb[(size_t)(m0 + r) * ldc + n0 + cc] = v;
        }
    } else {
        if (n0 < 256) {
            for (int u = t; u < 128 * 64; u += 256) {
                int r = u >> 6, wp = u & 63;
                int cc = 2 * wp;
                int dim = n0 + cc;
                int h = dim >> 5, w2 = (dim & 31) >> 1;
                int m = m0 + r;
                int b = m >> 10, key = m & 1023;
                g_KhW[((size_t)((b * 8 + h) * NS_ + key)) * 16 + w2] =
                    pkh2(epi[r * ES + cc], epi[r * ES + cc + 1]);
            }
        } else {
            for (int u = t; u < 64 * 128; u += 256) {
                int wl = u >> 7, cc = u & 127;
                int dim = n0 - 256 + cc;
                int h = dim >> 5, d = dim & 31;
                int m = m0 + 2 * wl;
                int b = m >> 10, keyloc = m & 1023;
                g_VtW[((size_t)((b * 8 + h) * 32 + d)) * 512 + (keyloc >> 1)] =
                    pkh2(epi[(2 * wl) * ES + cc], epi[(2 * wl + 1) * ES + cc]);
            }
        }
    }
#undef GB_LOAD
#undef GB_STORE
}

// ---- merged conv(split-K x4) + q-projection launch ----------------------------
// grid (2, 144, 4): y<16 conv m-tile y (all z); y in [16,144) -> qproj (z==0)
__global__ void __launch_bounds__(256, 1)
conv_q_kernel(const float* __restrict__ x) {
    if (blockIdx.y < 16) {
        int zh = blockIdx.z;
        gemm_body<128, 2, 4, true, 0>(
            nullptr, 0, zh * KCH_, g_WcP, KCOL_ / 2,
            g_CPart + (size_t)zh * (B_ * NS_ * C_), C_,
            KCH_, nullptr, blockIdx.x * 128, blockIdx.y * 128);
    } else {
        if (blockIdx.z) return;
        gemm_body<128, 2, 4, false, 0>(
            x, C_, 0, g_WqP, 128, g_Q, C_,
            C_, nullptr, blockIdx.x * 128, (blockIdx.y - 16) * 128);
    }
}

// out projection
__global__ void __launch_bounds__(256, 1)
out_gemm_kernel(const float* __restrict__ A, float* __restrict__ out,
                const float* __restrict__ bias) {
    gemm_body<128, 2, 4, false, 0>(A, C_, 0, g_WpP, 128, out, C_, C_, bias,
                                   blockIdx.x * 128, blockIdx.y * 128);
}

// KV projection with packing epilogue
__global__ void __launch_bounds__(256, 1)
kv_gemm_kernel(const float* __restrict__ A) {
    gemm_body<128, 2, 4, false, 2>(A, C_, 0, g_WkvP, 128, nullptr, 0, C_, nullptr,
                                   blockIdx.x * 128, blockIdx.y * 128);
}

// ================= fused flash attention (R15, verified) ======================
__global__ void __launch_bounds__(256, 2)
attn_fused(const float* __restrict__ conf) {
    extern __shared__ float smem[];
    uint32_t* QhW = (uint32_t*)smem;            // [128][20]
    uint32_t* QlW = QhW + 128 * 20;
    uint32_t* stg = QlW + 128 * 20;             // 2 stages: [128*20 K][32*68 V][128 conf]
    const int STW = 128 * 20 + 32 * 68 + 128;

    const int t = threadIdx.x, lane = t & 31, warp = t >> 5;
    const int g = lane >> 2, tig = lane & 3;
    const int bh = blockIdx.y, b = bh >> 3, h = bh & 7;
    const int m0 = blockIdx.x << 7;
    const int wrb = warp << 4;
    const float scale = 0.17677669529663687f;

    const int lrow = (lane & 7) | (((lane >> 3) & 1) << 3);
    const int lwof4 = (lane >> 4) << 2;
    const int browb = lane & 7;
    const int bwof4 = ((lane >> 3) & 1) << 2;

    {
        const int lr = t >> 3, lc = (t & 7) * 4;
#pragma unroll
        for (int i = 0; i < 4; i++) {
            int r = lr + i * 32;
            float4 v = *(const float4*)(g_Q + (size_t)(b * N_ + m0 + r) * C_ + h * DH_ + lc);
            float h0, l0, h1, l1, h2, l2, h3, l3;
            f16split(v.x * scale, h0, l0); f16split(v.y * scale, h1, l1);
            f16split(v.z * scale, h2, l2); f16split(v.w * scale, h3, l3);
            *(uint2*)&QhW[r * 20 + (lc >> 1)] = make_uint2(pkh2(h0, h1), pkh2(h2, h3));
            *(uint2*)&QlW[r * 20 + (lc >> 1)] = make_uint2(pkh2(l0, l1), pkh2(l2, l3));
        }
    }

    float Oacc[4][4];
#pragma unroll
    for (int i = 0; i < 4; i++)
#pragma unroll
        for (int j = 0; j < 4; j++) Oacc[i][j] = 0.f;
    float l0s = 0.f, l1s = 0.f;

    const uint4* KhG = (const uint4*)g_KhW;
    const uint4* VtG = (const uint4*)g_VtW;
    uint4 kr[2], vr[2];
    float cf;

#define AT_LOAD(kc_)                                                              \
    {                                                                             \
        int kb_ = (kc_) << 7;                                                     \
        _Pragma("unroll")                                                         \
        for (int i = 0; i < 2; i++) {                                             \
            int u = t + i * 256;                                                  \
            kr[i] = KhG[(size_t)(bh * NS_ + kb_ + (u >> 2)) * 4 + (u & 3)];       \
            vr[i] = VtG[(size_t)(bh * 32 + (u >> 4)) * 128 + (kc_) * 16 + (u & 15)]; \
        }                                                                         \
        if (t < 128) cf = conf[b * NS_ + kb_ + t];                                \
    }

#define AT_STORE(st_)                                                             \
    {                                                                             \
        uint32_t* KsW_ = stg + (st_) * STW;                                       \
        uint32_t* VsW_ = KsW_ + 128 * 20;                                         \
        float* cf_ = (float*)(VsW_ + 32 * 68);                                    \
        _Pragma("unroll")                                                         \
        for (int i = 0; i < 2; i++) {                                             \
            int u = t + i * 256;                                                  \
            *(uint4*)&KsW_[(u >> 2) * 20 + 4 * (u & 3)] = kr[i];                  \
            *(uint4*)&VsW_[(u >> 4) * 68 + 4 * (u & 15)] = vr[i];                 \
        }                                                                         \
        if (t < 128) cf_[t] = cf;                                                 \
    }

    AT_LOAD(0);
    AT_STORE(0);
    __syncthreads();
    AT_LOAD(1);

    const uint32_t qh_b = s2u(QhW);
    const uint32_t ql_b = s2u(QlW);

    for (int kc = 0; kc < 8; kc++) {
        const int st = kc & 1;
        uint32_t* KsW = stg + st * STW;
        uint32_t* VsW = KsW + 128 * 20;
        const float* confs = (const float*)(VsW + 32 * 68);
        const uint32_t k_b = s2u(KsW);
        const uint32_t v_b = s2u(VsW);

#pragma unroll
        for (int h2 = 0; h2 < 2; h2++) {
            float Sacc[8][4];
#pragma unroll
            for (int nt = 0; nt < 8; nt++)
#pragma unroll
                for (int q = 0; q < 4; q++) Sacc[nt][q] = 0.f;

#pragma unroll
            for (int ks = 0; ks < 2; ks++) {
                const int w0 = ks * 8;
                uint32_t ah[4], al[4];
                uint32_t aoff = (uint32_t)(((wrb + lrow) * 20 + w0 + lwof4) * 4);
                ldsm_x4(ah, qh_b + aoff);
                ldsm_x4(al, ql_b + aoff);
#pragma unroll
                for (int nt = 0; nt < 8; nt++) {
                    uint32_t bv[2];
                    uint32_t boff = (uint32_t)((((h2 * 8 + nt) * 8 + browb) * 20 + w0 + bwof4) * 4);
                    ldsm_x2(bv, k_b + boff);
                    mma16(Sacc[nt], ah, bv);
                    mma16(Sacc[nt], al, bv);
                }
            }

#pragma unroll
            for (int jj = 0; jj < 4; jj++) {
                const int j = h2 * 4 + jj;
                const int nt0 = 2 * jj, nt1 = 2 * jj + 1;
                const int ng0 = h2 * 8 + nt0, ng1 = h2 * 8 + nt1;
                float ca0 = confs[ng0 * 8 + 2 * tig], cb0 = confs[ng0 * 8 + 2 * tig + 1];
                float ca1 = confs[ng1 * 8 + 2 * tig], cb1 = confs[ng1 * 8 + 2 * tig + 1];
                float p00 = __expf(Sacc[nt0][0] + ca0);
                float p01 = __expf(Sacc[nt0][1] + cb0);
                float p02 = __expf(Sacc[nt0][2] + ca0);
                float p03 = __expf(Sacc[nt0][3] + cb0);
                float p10 = __expf(Sacc[nt1][0] + ca1);
                float p11 = __expf(Sacc[nt1][1] + cb1);
                float p12 = __expf(Sacc[nt1][2] + ca1);
                float p13 = __expf(Sacc[nt1][3] + cb1);
                l0s += p00 + p01 + p10 + p11;
                l1s += p02 + p03 + p12 + p13;

                uint32_t a[4];
                a[0] = pkh2(p00, p01);
                a[1] = pkh2(p02, p03);
                a[2] = pkh2(p10, p11);
                a[3] = pkh2(p12, p13);
#pragma unroll
                for (int dt = 0; dt < 4; dt++) {
                    uint32_t bv[2];
                    uint32_t boff = (uint32_t)(((dt * 8 + browb) * 68 + 8 * j + bwof4) * 4);
                    ldsm_x2(bv, v_b + boff);
                    mma16(Oacc[dt], a, bv);
                }
            }
        }

        if (kc + 1 < 8) {
            AT_STORE(st ^ 1);
            __syncthreads();
            if (kc + 2 < 8) AT_LOAD(kc + 2);
        }
    }
#undef AT_LOAD
#undef AT_STORE

    l0s += __shfl_xor_sync(~0u, l0s, 1); l0s += __shfl_xor_sync(~0u, l0s, 2);
    l1s += __shfl_xor_sync(~0u, l1s, 1); l1s += __shfl_xor_sync(~0u, l1s, 2);
    float r0inv = 1.f / l0s, r1inv = 1.f / l1s;

#pragma unroll
    for (int dt = 0; dt < 4; dt++) {
        int cc = h * DH_ + dt * 8 + 2 * tig;
        size_t rowa = (size_t)(b * N_ + m0 + wrb + g) * C_;
        size_t rowb = (size_t)(b * N_ + m0 + wrb + 8 + g) * C_;
        g_AO[rowa + cc]     = Oacc[dt][0] * r0inv;
        g_AO[rowa + cc + 1] = Oacc[dt][1] * r0inv;
        g_AO[rowb + cc]     = Oacc[dt][2] * r1inv;
        g_AO[rowb + cc + 1] = Oacc[dt][3] * r1inv;
    }
}

// ================= preprocessing ==============================================
__global__ void __launch_bounds__(256) scatter_kernel(const float* __restrict__ xs,
                                                      const float* __restrict__ loc) {
    const int tok0 = blockIdx.x << 3;
    const int c = threadIdx.x;
    int p[8];
#pragma unroll
    for (int i = 0; i < 8; i++) {
        int token = tok0 + i;
        int b = token >> 13;
        float lx = loc[(size_t)token * 2 + 0];
        float ly = loc[(size_t)token * 2 + 1];
        lx = fminf(fmaxf(lx, 0.f), 1.f) * 127.f;
        ly = fminf(fmaxf(ly, 0.f), 1.f) * 127.f;
        p[i] = (b << 14) + (int)rintf(ly) * HM_ + (int)rintf(lx);
    }
#pragma unroll
    for (int i = 0; i < 8; i++) {
        atomicAdd(&g_Fmap[(size_t)p[i] * C_ + c], xs[(size_t)(tok0 + i) * C_ + c]);
        if (c == 0) atomicAdd(&g_Cnt[p[i]], 1.0f);
    }
}

__global__ void __launch_bounds__(256) blur_fused_kernel() {
    __shared__ float sf[3][34][64];
    __shared__ float minv[3][34];
    __shared__ float msk[3][34];

    const int t = threadIdx.x;
    const int x0 = blockIdx.x << 5;
    const int y = blockIdx.y;
    const int b = blockIdx.z >> 2, cg = blockIdx.z & 3;
    const int cbase = cg << 6;

    if (t < 102) {
        int r = t / 34, px = t % 34;
        int gy = y + r - 1, gx = x0 + px - 1;
        float inv = 0.f, mk = 0.f;
        if (gy >= 0 && gy < HM_ && gx >= 0 && gx < HM_) {
            float cnt = g_Cnt[(b << 14) + gy * HM_ + gx];
            if (cnt > 0.f) { inv = 1.f / (cnt + 1e-6f); mk = 1.f; }
        }
        minv[r][px] = inv;
        msk[r][px] = mk;
    }
    __syncthreads();

    for (int idx = t; idx < 3 * 34 * 64; idx += 256) {
        int r = idx / (34 * 64);
        int rem = idx - r * (34 * 64);
        int px = rem >> 6, c = rem & 63;
        int gy = y + r - 1, gx = x0 + px - 1;
        float val = 0.f;
        if (gy >= 0 && gy < HM_ && gx >= 0 && gx < HM_) {
            int pix = (b << 14) + gy * HM_ + gx;
            val = g_Fmap[(size_t)pix * 256 + cbase + c] * minv[r][px];
        }
        sf[r][px][c] = val;
    }
    __syncthreads();

    const float e1 = 0.88249690258459546f;
    const float e2 = 0.77880078307140487f;
    const float nrm = 1.0f / (1.0f + 4.0f * e1 + 4.0f * e2);
    const float wc = nrm, we = e1 * nrm, wo = e2 * nrm;

    const int c = t & 63;
    const int pg = t >> 6;
#pragma unroll
    for (int i = 0; i < 8; i++) {
        int px = pg * 8 + i;
        int ps = px + 1;
        float msum =
            wo * (msk[0][ps - 1] + msk[0][ps + 1] + msk[2][ps - 1] + msk[2][ps + 1]) +
            we * (msk[0][ps] + msk[1][ps - 1] + msk[1][ps + 1] + msk[2][ps]) +
            wc * msk[1][ps];
        float fsum =
            wo * (sf[0][ps - 1][c] + sf[0][ps + 1][c] + sf[2][ps - 1][c] + sf[2][ps + 1][c]) +
            we * (sf[0][ps][c] + sf[1][ps - 1][c] + sf[1][ps + 1][c] + sf[2][ps][c]) +
            wc * sf[1][ps][c];
        float fint = (msum > 0.f) ? fsum / (msum + 1e-6f) : 0.f;
        float fc = sf[1][ps][c];
        float mc = msk[1][ps];
        int cp = (b << 14) + y * HM_ + x0 + px;
        g_Xm[(size_t)cp * 256 + cbase + c] = fc + (1.f - mc) * fint;
    }
}

// weight prep: pack Wc (permuted), Wkv, Wq, Wp into f16 words
// total words: 524288 + 65536 + 32768 + 32768 = 655360 -> 2560 blocks
__global__ void __launch_bounds__(256) wprep_kernel(const float* __restrict__ srw,
                                                    const float* __restrict__ Wk,
                                                    const float* __restrict__ Wv,
                                                    const float* __restrict__ Wq,
                                                    const float* __restrict__ Wp) {
    int u = blockIdx.x * 256 + threadIdx.x;
    if (u < 524288) {
        int co = u >> 11, w = u & 2047;
        int kk = w >> 7, ci = 2 * (w & 127);
        g_WcP[u] = pkh2(srw[(size_t)co * 4096 + ci * 16 + kk],
                        srw[(size_t)co * 4096 + (ci + 1) * 16 + kk]);
    } else if (u < 524288 + 65536) {
        int v = u - 524288;
        int row = v >> 7, w = v & 127;
        const float* W = (row < 256) ? (Wk + (size_t)row * 256) : (Wv + (size_t)(row - 256) * 256);
        g_WkvP[v] = pkh2(W[2 * w], W[2 * w + 1]);
    } else if (u < 524288 + 65536 + 32768) {
        int v = u - 524288 - 65536;
        int row = v >> 7, w = v & 127;
        g_WqP[v] = pkh2(Wq[(size_t)row * 256 + 2 * w], Wq[(size_t)row * 256 + 2 * w + 1]);
    } else if (u < 655360) {
        int v = u - 524288 - 65536 - 32768;
        int row = v >> 7, w = v & 127;
        g_WpP[v] = pkh2(Wp[(size_t)row * 256 + 2 * w], Wp[(size_t)row * 256 + 2 * w + 1]);
    }
}

// LN over C; input = sum of split-K conv partials + sr_b
__global__ void __launch_bounds__(256) ln_kernel(const float* __restrict__ srb,
                                                 const float* __restrict__ lnw,
                                                 const float* __restrict__ lnb) {
    __shared__ float red[8];
    int row = blockIdx.x, c = threadIdx.x;
    int lane = c & 31, wrp = c >> 5;
    float v = srb[c];
#pragma unroll
    for (int s = 0; s < KSPL_; s++)
        v += g_CPart[(size_t)s * (B_ * NS_ * C_) + (size_t)row * C_ + c];
    float s = v;
#pragma unroll
    for (int o = 16; o; o >>= 1) s += __shfl_xor_sync(~0u, s, o);
    if (lane == 0) red[wrp] = s;
    __syncthreads();
    float mu = (red[0] + red[1] + red[2] + red[3] + red[4] + red[5] + red[6] + red[7]) * (1.f / 256.f);
    float d = v - mu;
    float s2 = d * d;
#pragma unroll
    for (int o = 16; o; o >>= 1) s2 += __shfl_xor_sync(~0u, s2, o);
    __syncthreads();
    if (lane == 0) red[wrp] = s2;
    __syncthreads();
    float var = (red[0] + red[1] + red[2] + red[3] + red[4] + red[5] + red[6] + red[7]) * (1.f / 256.f);
    g_Xs[(size_t)row * C_ + c] = d * rsqrtf(var + 1e-5f) * lnw[c] + lnb[c];
}

// ================= launch =====================================================
extern "C" void kernel_launch(void* const* d_in, const int* in_sizes, int n_in,
                              void* d_out, int out_size) {
    const float* x        = (const float*)d_in[0];
    const float* x_source = (const float*)d_in[1];
    const float* loc      = (const float*)d_in[2];
    const float* conf     = (const float*)d_in[3];
    const float* Wq       = (const float*)d_in[4];
    const float* Wk       = (const float*)d_in[5];
    const float* Wv       = (const float*)d_in[6];
    const float* sr_w     = (const float*)d_in[7];
    const float* sr_b     = (const float*)d_in[8];
    const float* ln_w     = (const float*)d_in[9];
    const float* ln_b     = (const float*)d_in[10];
    const float* Wp       = (const float*)d_in[11];
    const float* bp       = (const float*)d_in[12];
    float* out = (float*)d_out;

    float *pFmap, *pCnt, *pXs, *pAO;
    cudaGetSymbolAddress((void**)&pFmap, g_Fmap);
    cudaGetSymbolAddress((void**)&pCnt, g_Cnt);
    cudaGetSymbolAddress((void**)&pXs, g_Xs);
    cudaGetSymbolAddress((void**)&pAO, g_AO);

    const size_t SM128 = 67584;
    const size_t SMATT = 20480 + 2 * (128 * 20 + 32 * 68 + 128) * 4;
    cudaFuncSetAttribute((const void*)conv_q_kernel,
                         cudaFuncAttributeMaxDynamicSharedMemorySize, (int)SM128);
    cudaFuncSetAttribute((const void*)out_gemm_kernel,
                         cudaFuncAttributeMaxDynamicSharedMemorySize, (int)SM128);
    cudaFuncSetAttribute((const void*)kv_gemm_kernel,
                         cudaFuncAttributeMaxDynamicSharedMemorySize, (int)SM128);
    cudaFuncSetAttribute((const void*)attn_fused,
                         cudaFuncAttributeMaxDynamicSharedMemorySize, (int)SMATT);

    // token2map
    cudaMemsetAsync(pFmap, 0, (size_t)B_ * HW_ * C_ * sizeof(float));
    cudaMemsetAsync(pCnt, 0, (size_t)B_ * HW_ * sizeof(float));
    scatter_kernel<<<(B_ * N_) / 8, 256>>>(x_source, loc);
    blur_fused_kernel<<<dim3(4, HM_, B_ * 4), 256>>>();

    // weight prep (fp16 packing, one-time rn conversion)
    wprep_kernel<<<2560, 256>>>(sr_w, Wk, Wv, Wq, Wp);

    // conv (split-K x4, implicit im2col) + q projection, one launch
    conv_q_kernel<<<dim3(2, 144, 4), 256, SM128>>>(x);
    ln_kernel<<<B_ * NS_, 256>>>(sr_b, ln_w, ln_b);

    // fused k+v projection with packing epilogue
    kv_gemm_kernel<<<dim3(4, 16), 256, SM128>>>(pXs);

    // fused attention
    attn_fused<<<dim3(N_ / 128, B_ * HEADS_), 256, SMATT>>>(conf);

    // output projection (+bias)
    out_gemm_kernel<<<dim3(2, 128), 256, SM128>>>(pAO, out, bp);
}